// round 10
// baseline (speedup 1.0000x reference)
#include <cuda_runtime.h>
#include <cuda_fp16.h>
#include <stdint.h>

#define BATCH   8192
#define K_DIM   2048
#define O_DIM   2048

#define TM 256
#define TN 128
#define KC 64
#define NCHUNK (K_DIM / KC)   // 32

// ---------------- scratch (fp16) ----------------
__device__ __align__(128) __half g_At_hi[(size_t)O_DIM * K_DIM];  // W^T  [o][k]
__device__ __align__(128) __half g_X_hi[(size_t)BATCH * K_DIM];   // X    [b][k]

// ---------------- helpers ----------------
__device__ __forceinline__ uint32_t smem_u32(const void* p) {
    uint32_t a;
    asm("{ .reg .u64 t; cvta.to.shared.u64 t, %1; cvt.u32.u64 %0, t; }" : "=r"(a) : "l"(p));
    return a;
}
__device__ __forceinline__ void cp_async16(uint32_t dst, const void* src) {
    asm volatile("cp.async.cg.shared.global [%0], [%1], 16;" :: "r"(dst), "l"(src) : "memory");
}
__device__ __forceinline__ void cp_async_commit() {
    asm volatile("cp.async.commit_group;" ::: "memory");
}
__device__ __forceinline__ void cp_async_wait2() {
    asm volatile("cp.async.wait_group 2;" ::: "memory");
}
__device__ __forceinline__ void ldsm_x4(uint32_t* r, uint32_t addr) {
    asm volatile("ldmatrix.sync.aligned.m8n8.x4.shared.b16 {%0,%1,%2,%3}, [%4];"
                 : "=r"(r[0]), "=r"(r[1]), "=r"(r[2]), "=r"(r[3]) : "r"(addr));
}
__device__ __forceinline__ void mma_f32(float* c, const uint32_t* a, const uint32_t* b) {
    asm volatile(
        "mma.sync.aligned.m16n8k16.row.col.f32.f16.f16.f32 "
        "{%0,%1,%2,%3}, {%4,%5,%6,%7}, {%8,%9}, {%0,%1,%2,%3};"
        : "+f"(c[0]), "+f"(c[1]), "+f"(c[2]), "+f"(c[3])
        : "r"(a[0]), "r"(a[1]), "r"(a[2]), "r"(a[3]), "r"(b[0]), "r"(b[1]));
}
__device__ __forceinline__ uint32_t sw128(uint32_t off) {
    return off ^ ((off >> 3) & 0x70);
}

// ---------------- SMEM layout: 4 stages x 48KB ----------------
// per stage: Ah 32KB (256 rows x 128B) | Bh 16KB (128 rows x 128B)
#define ST_AH 0
#define ST_BH 32768
#define STAGE_BYTES 49152
#define SMEM_TOTAL (4 * STAGE_BYTES)   // 196608

// ---------------- merged conversion kernel ----------------
__global__ __launch_bounds__(256)
void convert_kernel(const float* __restrict__ x, const float* __restrict__ w) {
    int tid = threadIdx.x;
    if (blockIdx.x < 2048) {
        size_t base = (size_t)blockIdx.x * 2048 + tid;
#pragma unroll
        for (int it = 0; it < 8; it++) {
            size_t i = base + (size_t)it * 256;
            float4 v = reinterpret_cast<const float4*>(x)[i];
            __half2 a, b;
            a.x = __float2half(v.x); a.y = __float2half(v.y);
            b.x = __float2half(v.z); b.y = __float2half(v.w);
            __half2* H = reinterpret_cast<__half2*>(g_X_hi);
            H[2 * i] = a; H[2 * i + 1] = b;
        }
    } else {
        __shared__ float tile[32][33];
        int b = blockIdx.x - 2048;
        int o0 = (b & 63) * 32;
        int k0 = (b >> 6) * 32;
        int c = tid & 31, r8 = tid >> 5;
#pragma unroll
        for (int j = 0; j < 4; j++) {
            int r = r8 + 8 * j;
            tile[r][c] = w[(size_t)(k0 + r) * O_DIM + o0 + c];
        }
        __syncthreads();
#pragma unroll
        for (int j = 0; j < 4; j++) {
            int a = r8 + 8 * j;     // o offset
            float f = tile[c][a];   // w[k0+c][o0+a]
            g_At_hi[(size_t)(o0 + a) * K_DIM + (k0 + c)] = __float2half(f);
        }
    }
}

// ---------------- GEMM ----------------
// 256 threads. Stage = 384 logical rows of 128B: Ah [0,256), Bh [256,384).
// 12 iters: row = it*32 + tid/8, col = tid%8 (8 lanes span one 128B row ->
// 4 gmem lines per warp instruction, fully coalesced)
__device__ __forceinline__ void issue_stage(uint32_t sbase, int o0, int b0, int chunk, int tid) {
    uint32_t st = sbase + (uint32_t)(chunk & 3) * STAGE_BYTES;
    int k0 = chunk * KC;
    int rsub = tid >> 3;        // 0..31
    int col = tid & 7;          // 16B column
#pragma unroll
    for (int it = 0; it < 12; it++) {
        int row = it * 32 + rsub;
        const __half* src;
        uint32_t dstb;
        int grow, lrow;
        if (it < 8) { src = g_At_hi; dstb = st + ST_AH; grow = o0 + row;       lrow = row; }
        else        { src = g_X_hi;  dstb = st + ST_BH; grow = b0 + row - 256; lrow = row - 256; }
        const char* g = (const char*)(src + (size_t)grow * K_DIM + k0) + col * 16;
        cp_async16(dstb + sw128((uint32_t)lrow * 128 + col * 16), g);
    }
}

__global__ __launch_bounds__(256, 1)
void gemm_kernel(float* __restrict__ out) {
    extern __shared__ char smem[];
    uint32_t sbase = smem_u32(smem);
    int tid = threadIdx.x;
    int wid = tid >> 5, lane = tid & 31;
    int o0 = blockIdx.x * TM;
    int b0 = blockIdx.y * TN;
    int wm = (wid >> 1) * 64;   // 4 warp rows (M)
    int wn = (wid & 1) * 64;    // 2 warp cols (N)

    float c[4][8][4];   // warp tile 64x64, fp32 acc
#pragma unroll
    for (int i = 0; i < 4; i++)
#pragma unroll
        for (int j = 0; j < 8; j++)
#pragma unroll
            for (int q = 0; q < 4; q++) c[i][j][q] = 0.0f;

    issue_stage(sbase, o0, b0, 0, tid); cp_async_commit();
    issue_stage(sbase, o0, b0, 1, tid); cp_async_commit();
    issue_stage(sbase, o0, b0, 2, tid); cp_async_commit();

    int a_row = lane & 15;
    int a_cb  = (lane >> 4) << 4;
    int b_row = ((lane >> 4) << 3) + (lane & 7);
    int b_cb  = ((lane >> 3) & 1) << 4;

    for (int i = 0; i < NCHUNK; i++) {
        cp_async_wait2();
        __syncthreads();
        if (i + 3 < NCHUNK) issue_stage(sbase, o0, b0, i + 3, tid);
        cp_async_commit();

        uint32_t st = sbase + (uint32_t)(i & 3) * STAGE_BYTES;
#pragma unroll
        for (int kk = 0; kk < 4; kk++) {
            uint32_t ah[4][4];
#pragma unroll
            for (int mt = 0; mt < 4; mt++) {
                uint32_t off = (uint32_t)(wm + mt * 16 + a_row) * 128 + kk * 32 + a_cb;
                ldsm_x4(ah[mt], st + ST_AH + sw128(off));
            }
#pragma unroll
            for (int nt = 0; nt < 4; nt++) {
                uint32_t off = (uint32_t)(wn + nt * 16 + b_row) * 128 + kk * 32 + b_cb;
                uint32_t bh[4];
                ldsm_x4(bh, st + ST_BH + sw128(off));
#pragma unroll
                for (int mt = 0; mt < 4; mt++) {
                    mma_f32(c[mt][2 * nt],     ah[mt], bh);
                    mma_f32(c[mt][2 * nt + 1], ah[mt], bh + 2);
                }
            }
        }
        // no trailing sync: next iteration's leading __syncthreads orders
        // this iteration's smem reads before the slot is rewritten
    }

    // epilogue
    int r0 = o0 + wm + (lane >> 2);
    int col0 = b0 + wn + (lane & 3) * 2;
#pragma unroll
    for (int mt = 0; mt < 4; mt++) {
#pragma unroll
        for (int nt = 0; nt < 8; nt++) {
            int row = r0 + mt * 16;
            int col = col0 + nt * 8;
            float2 v0; v0.x = c[mt][nt][0]; v0.y = c[mt][nt][1];
            float2 v1; v1.x = c[mt][nt][2]; v1.y = c[mt][nt][3];
            *reinterpret_cast<float2*>(out + (size_t)row * BATCH + col) = v0;
            *reinterpret_cast<float2*>(out + (size_t)(row + 8) * BATCH + col) = v1;
        }
    }
}

// ---------------- launch ----------------
extern "C" void kernel_launch(void* const* d_in, const int* in_sizes, int n_in,
                              void* d_out, int out_size) {
    const float* in_values = (const float*)d_in[0];   // [8192, 2048]
    const float* weights   = (const float*)d_in[1];   // [2048, 2048]
    // d_in[2] = bias: intentionally unused (reference discards the add)
    float* out = (float*)d_out;                        // [2048, 8192]

    cudaFuncSetAttribute(gemm_kernel, cudaFuncAttributeMaxDynamicSharedMemorySize, SMEM_TOTAL);

    convert_kernel<<<6144, 256>>>(in_values, weights);
    gemm_kernel<<<dim3(O_DIM / TM, BATCH / TN), 256, SMEM_TOTAL>>>(out);
}

// round 11
// speedup vs baseline: 1.2073x; 1.2073x over previous
#include <cuda_runtime.h>
#include <cuda_fp16.h>
#include <stdint.h>

#define BATCH   8192
#define K_DIM   2048
#define O_DIM   2048

#define TM 128
#define TN 128
#define KC 64
#define NCHUNK (K_DIM / KC)   // 32

// ---------------- scratch (fp16) ----------------
__device__ __align__(128) __half g_At_hi[(size_t)O_DIM * K_DIM];  // W^T  [o][k]
__device__ __align__(128) __half g_X_hi[(size_t)BATCH * K_DIM];   // X    [b][k]

// ---------------- helpers ----------------
__device__ __forceinline__ uint32_t smem_u32(const void* p) {
    uint32_t a;
    asm("{ .reg .u64 t; cvta.to.shared.u64 t, %1; cvt.u32.u64 %0, t; }" : "=r"(a) : "l"(p));
    return a;
}
__device__ __forceinline__ void cp_async16(uint32_t dst, const void* src) {
    asm volatile("cp.async.cg.shared.global [%0], [%1], 16;" :: "r"(dst), "l"(src) : "memory");
}
__device__ __forceinline__ void cp_async_commit() {
    asm volatile("cp.async.commit_group;" ::: "memory");
}
__device__ __forceinline__ void cp_async_wait1() {
    asm volatile("cp.async.wait_group 1;" ::: "memory");
}
__device__ __forceinline__ void ldsm_x4(uint32_t* r, uint32_t addr) {
    asm volatile("ldmatrix.sync.aligned.m8n8.x4.shared.b16 {%0,%1,%2,%3}, [%4];"
                 : "=r"(r[0]), "=r"(r[1]), "=r"(r[2]), "=r"(r[3]) : "r"(addr));
}
__device__ __forceinline__ void mma_f32(float* c, const uint32_t* a, const uint32_t* b) {
    asm volatile(
        "mma.sync.aligned.m16n8k16.row.col.f32.f16.f16.f32 "
        "{%0,%1,%2,%3}, {%4,%5,%6,%7}, {%8,%9}, {%0,%1,%2,%3};"
        : "+f"(c[0]), "+f"(c[1]), "+f"(c[2]), "+f"(c[3])
        : "r"(a[0]), "r"(a[1]), "r"(a[2]), "r"(a[3]), "r"(b[0]), "r"(b[1]));
}
__device__ __forceinline__ uint32_t sw128(uint32_t off) {
    return off ^ ((off >> 3) & 0x70);
}

// ---------------- SMEM layout: 3 stages x 32KB = 96KB (2 CTAs/SM) ----------------
// per stage: A 16KB (128 rows x 128B) | B 16KB (128 rows x 128B)
#define ST_A 0
#define ST_B 16384
#define STAGE_BYTES 32768
#define SMEM_TOTAL (3 * STAGE_BYTES)   // 98304

// ---------------- merged conversion kernel ----------------
__global__ __launch_bounds__(256)
void convert_kernel(const float* __restrict__ x, const float* __restrict__ w) {
    int tid = threadIdx.x;
    if (blockIdx.x < 2048) {
        size_t base = (size_t)blockIdx.x * 2048 + tid;
#pragma unroll
        for (int it = 0; it < 8; it++) {
            size_t i = base + (size_t)it * 256;
            float4 v = reinterpret_cast<const float4*>(x)[i];
            __half2 a, b;
            a.x = __float2half(v.x); a.y = __float2half(v.y);
            b.x = __float2half(v.z); b.y = __float2half(v.w);
            __half2* H = reinterpret_cast<__half2*>(g_X_hi);
            H[2 * i] = a; H[2 * i + 1] = b;
        }
    } else {
        __shared__ float tile[32][33];
        int b = blockIdx.x - 2048;
        int o0 = (b & 63) * 32;
        int k0 = (b >> 6) * 32;
        int c = tid & 31, r8 = tid >> 5;
#pragma unroll
        for (int j = 0; j < 4; j++) {
            int r = r8 + 8 * j;
            tile[r][c] = w[(size_t)(k0 + r) * O_DIM + o0 + c];
        }
        __syncthreads();
#pragma unroll
        for (int j = 0; j < 4; j++) {
            int a = r8 + 8 * j;     // o offset
            float f = tile[c][a];   // w[k0+c][o0+a]
            g_At_hi[(size_t)(o0 + a) * K_DIM + (k0 + c)] = __float2half(f);
        }
    }
}

// ---------------- GEMM ----------------
// 256 threads. Stage = 256 logical rows of 128B: A [0,128), B [128,256).
// 8 iters: row = it*32 + tid/8, col = tid%8  (8 lanes span one full 128B row
// -> 4 gmem lines per warp instruction, fully coalesced)
__device__ __forceinline__ void issue_stage(uint32_t sbase, int o0, int b0, int chunk, int tid) {
    uint32_t st = sbase + (uint32_t)(chunk % 3) * STAGE_BYTES;
    int k0 = chunk * KC;
    int rsub = tid >> 3;        // 0..31
    int col = tid & 7;          // 16B column
#pragma unroll
    for (int it = 0; it < 8; it++) {
        int row = it * 32 + rsub;
        const __half* src;
        uint32_t dstb;
        int grow, lrow;
        if (it < 4) { src = g_At_hi; dstb = st + ST_A; grow = o0 + row;       lrow = row; }
        else        { src = g_X_hi;  dstb = st + ST_B; grow = b0 + row - 128; lrow = row - 128; }
        const char* g = (const char*)(src + (size_t)grow * K_DIM + k0) + col * 16;
        cp_async16(dstb + sw128((uint32_t)lrow * 128 + col * 16), g);
    }
}

__global__ __launch_bounds__(256, 2)
void gemm_kernel(float* __restrict__ out) {
    extern __shared__ char smem[];
    uint32_t sbase = smem_u32(smem);
    int tid = threadIdx.x;
    int wid = tid >> 5, lane = tid & 31;
    int o0 = blockIdx.x * TM;
    int b0 = blockIdx.y * TN;
    int wm = (wid >> 2) * 64;   // 2 warp rows (M)
    int wn = (wid & 3) * 32;    // 4 warp cols (N)

    float c[4][4][4];   // warp tile 64x32, fp32 acc
#pragma unroll
    for (int i = 0; i < 4; i++)
#pragma unroll
        for (int j = 0; j < 4; j++)
#pragma unroll
            for (int q = 0; q < 4; q++) c[i][j][q] = 0.0f;

    issue_stage(sbase, o0, b0, 0, tid); cp_async_commit();
    issue_stage(sbase, o0, b0, 1, tid); cp_async_commit();

    int a_row = lane & 15;
    int a_cb  = (lane >> 4) << 4;
    int b_row = ((lane >> 4) << 3) + (lane & 7);
    int b_cb  = ((lane >> 3) & 1) << 4;

    for (int i = 0; i < NCHUNK; i++) {
        cp_async_wait1();
        __syncthreads();
        if (i + 2 < NCHUNK) issue_stage(sbase, o0, b0, i + 2, tid);
        cp_async_commit();

        uint32_t st = sbase + (uint32_t)(i % 3) * STAGE_BYTES;
#pragma unroll
        for (int kk = 0; kk < 4; kk++) {
            uint32_t ah[4][4];
#pragma unroll
            for (int mt = 0; mt < 4; mt++) {
                uint32_t off = (uint32_t)(wm + mt * 16 + a_row) * 128 + kk * 32 + a_cb;
                ldsm_x4(ah[mt], st + ST_A + sw128(off));
            }
#pragma unroll
            for (int nt = 0; nt < 2; nt++) {
                uint32_t off = (uint32_t)(wn + nt * 16 + b_row) * 128 + kk * 32 + b_cb;
                uint32_t bh[4];
                ldsm_x4(bh, st + ST_B + sw128(off));
#pragma unroll
                for (int mt = 0; mt < 4; mt++) {
                    mma_f32(c[mt][2 * nt],     ah[mt], bh);
                    mma_f32(c[mt][2 * nt + 1], ah[mt], bh + 2);
                }
            }
        }
        // no trailing sync: next iteration's leading __syncthreads orders
        // this iteration's smem reads before the slot is rewritten
    }

    // epilogue
    int r0 = o0 + wm + (lane >> 2);
    int col0 = b0 + wn + (lane & 3) * 2;
#pragma unroll
    for (int mt = 0; mt < 4; mt++) {
#pragma unroll
        for (int nt = 0; nt < 4; nt++) {
            int row = r0 + mt * 16;
            int col = col0 + nt * 8;
            float2 v0; v0.x = c[mt][nt][0]; v0.y = c[mt][nt][1];
            float2 v1; v1.x = c[mt][nt][2]; v1.y = c[mt][nt][3];
            *reinterpret_cast<float2*>(out + (size_t)row * BATCH + col) = v0;
            *reinterpret_cast<float2*>(out + (size_t)(row + 8) * BATCH + col) = v1;
        }
    }
}

// ---------------- launch ----------------
extern "C" void kernel_launch(void* const* d_in, const int* in_sizes, int n_in,
                              void* d_out, int out_size) {
    const float* in_values = (const float*)d_in[0];   // [8192, 2048]
    const float* weights   = (const float*)d_in[1];   // [2048, 2048]
    // d_in[2] = bias: intentionally unused (reference discards the add)
    float* out = (float*)d_out;                        // [2048, 8192]

    cudaFuncSetAttribute(gemm_kernel, cudaFuncAttributeMaxDynamicSharedMemorySize, SMEM_TOTAL);

    convert_kernel<<<6144, 256>>>(in_values, weights);
    gemm_kernel<<<dim3(O_DIM / TM, BATCH / TN), 256, SMEM_TOTAL>>>(out);
}